// round 10
// baseline (speedup 1.0000x reference)
#include <cuda_runtime.h>
#include <cuda_fp16.h>
#include <mma.h>
#include <cstdint>

using namespace nvcuda;

#define NT 20000
#define NC 80000
#define DIM 256
#define E_T2C 320000
#define E_C2T 320000
#define E_C2C 640000
#define E_T2T 160000

// ---------------- scratch (device globals; no allocations allowed) ----------
__device__ __half g_feat16[(size_t)(NT + NC) * DIM];       // [table | column]
__device__ __half g_W16[5 * DIM * DIM];                    // t2c,c2t,c2c,t2t,h
__device__ __half g_Wh_t2c[(size_t)NT * DIM];
__device__ __half g_Wh_c2t[(size_t)NC * DIM];
__device__ __half g_Wh_c2c[(size_t)NC * DIM];
__device__ __half g_Wh_t2t[(size_t)NT * DIM];
__device__ __half g_h16[(size_t)(NT + NC) * DIM];

#define CNT_T2C 0
#define CNT_C2T NC
#define CNT_C2C (NC + NT)
#define CNT_T2T (NC + NT + NC)
#define CNT_TOTAL (2 * NC + 2 * NT)
__device__ int g_cnt[CNT_TOTAL];
__device__ int g_off_t2c[NC + 1]; __device__ int g_pos_t2c[NC]; __device__ int g_e_t2c[E_T2C];
__device__ int g_off_c2t[NT + 1]; __device__ int g_pos_c2t[NT]; __device__ int g_e_c2t[E_C2T];
__device__ int g_off_c2c[NC + 1]; __device__ int g_pos_c2c[NC]; __device__ int g_e_c2c[E_C2C];
__device__ int g_off_t2t[NT + 1]; __device__ int g_pos_t2t[NT]; __device__ int g_e_t2t[E_T2T];

// scan partials: chunks per etype: NC->79, NT->20, NC->79, NT->20
#define NCH0 79
#define NCH1 20
#define NCH2 79
#define NCH3 20
#define NCH_TOTAL (NCH0 + NCH1 + NCH2 + NCH3)   // 198
__device__ int g_part[NCH_TOTAL];

// ---------------- helpers ----------------------------------------------------
__device__ __forceinline__ uint32_t smem_u32(const void* p) {
    uint32_t a;
    asm("{ .reg .u64 t; cvta.to.shared.u64 t, %1; cvt.u32.u64 %0, t; }" : "=r"(a) : "l"(p));
    return a;
}
#define CP_ASYNC16(dst, src) \
    asm volatile("cp.async.cg.shared.global [%0], [%1], 16;" :: "r"(dst), "l"(src))
#define CP_COMMIT() asm volatile("cp.async.commit_group;" ::: "memory")
#define CP_WAIT1() asm volatile("cp.async.wait_group 1;" ::: "memory")
#define CP_WAIT0() asm volatile("cp.async.wait_group 0;" ::: "memory")

__device__ __forceinline__ int warp_iscan(int v, int lane) {
    #pragma unroll
    for (int ofs = 1; ofs < 32; ofs <<= 1) {
        int t = __shfl_up_sync(0xffffffffu, v, ofs);
        if (lane >= ofs) v += t;
    }
    return v;
}

__device__ __forceinline__ void scan_map(int b, int& base, int& n, int& ch) {
    if (b < NCH0)                      { base = CNT_T2C; n = NC; ch = b; }
    else if (b < NCH0 + NCH1)          { base = CNT_C2T; n = NT; ch = b - NCH0; }
    else if (b < NCH0 + NCH1 + NCH2)   { base = CNT_C2C; n = NC; ch = b - NCH0 - NCH1; }
    else                               { base = CNT_T2T; n = NT; ch = b - NCH0 - NCH1 - NCH2; }
}

// ---------------- conversion kernels -----------------------------------------
__global__ void cvt_feat_kernel(const float* __restrict__ ft, const float* __restrict__ fc,
                                __half* __restrict__ dst) {
    int i = blockIdx.x * blockDim.x + threadIdx.x;
    const int n4T = NT * DIM / 4;
    const int n4 = (NT + NC) * DIM / 4;
    if (i >= n4) return;
    float4 v = (i < n4T) ? ((const float4*)ft)[i] : ((const float4*)fc)[i - n4T];
    half2* d2 = (half2*)dst;
    d2[2 * i]     = __floats2half2_rn(v.x, v.y);
    d2[2 * i + 1] = __floats2half2_rn(v.z, v.w);
}

__global__ void cvt_w_kernel(const float* __restrict__ w0, const float* __restrict__ w1,
                             const float* __restrict__ w2, const float* __restrict__ w3,
                             const float* __restrict__ w4, __half* __restrict__ dst) {
    int i = blockIdx.x * blockDim.x + threadIdx.x;
    if (i >= 5 * 16384) return;
    const float* srcs[5] = {w0, w1, w2, w3, w4};
    const float* s = srcs[i >> 14];
    int j = i & 16383;
    float4 v = ((const float4*)s)[j];
    half2* d2 = (half2*)dst;
    d2[2 * i]     = __floats2half2_rn(v.x, v.y);
    d2[2 * i + 1] = __floats2half2_rn(v.z, v.w);
}

// ---------------- graph preprocessing ----------------------------------------
__global__ void hist4_kernel(const int* __restrict__ d0, const int* __restrict__ d1,
                             const int* __restrict__ d2, const int* __restrict__ d3,
                             int* __restrict__ cnt,
                             int E0, int E1, int E2, int E3) {
    int i = blockIdx.x * blockDim.x + threadIdx.x;
    if (i < E0) { atomicAdd(&cnt[CNT_T2C + d0[i]], 1); return; }
    i -= E0;
    if (i < E1) { atomicAdd(&cnt[CNT_C2T + d1[i]], 1); return; }
    i -= E1;
    if (i < E2) { atomicAdd(&cnt[CNT_C2C + d2[i]], 1); return; }
    i -= E2;
    if (i < E3) { atomicAdd(&cnt[CNT_T2T + d3[i]], 1); }
}

__global__ void scan_part_kernel(const int* __restrict__ cntbase, int* __restrict__ part) {
    int base, n, ch;
    scan_map(blockIdx.x, base, n, ch);
    const int tid = threadIdx.x, lane = tid & 31, warp = tid >> 5;
    int i = ch * 1024 + tid;
    int v = (i < n) ? cntbase[base + i] : 0;
    #pragma unroll
    for (int ofs = 16; ofs > 0; ofs >>= 1) v += __shfl_down_sync(0xffffffffu, v, ofs);
    __shared__ int ws[32];
    if (lane == 0) ws[warp] = v;
    __syncthreads();
    if (warp == 0) {
        int s = ws[lane];
        #pragma unroll
        for (int ofs = 16; ofs > 0; ofs >>= 1) s += __shfl_down_sync(0xffffffffu, s, ofs);
        if (lane == 0) part[blockIdx.x] = s;
    }
}

__global__ void scan_mid_kernel(int* __restrict__ part,
                                int* o0, int* o1, int* o2, int* o3) {
    __shared__ int sh[NCH_TOTAL];
    const int tid = threadIdx.x;
    for (int i = tid; i < NCH_TOTAL; i += blockDim.x) sh[i] = part[i];
    __syncthreads();
    if (tid == 0) {
        const int bnd[5] = {0, NCH0, NCH0 + NCH1, NCH0 + NCH1 + NCH2, NCH_TOTAL};
        int* offs[4] = {o0, o1, o2, o3};
        const int nlist[4] = {NC, NT, NC, NT};
        for (int e = 0; e < 4; e++) {
            int run = 0;
            for (int b = bnd[e]; b < bnd[e + 1]; b++) { int v = sh[b]; sh[b] = run; run += v; }
            offs[e][nlist[e]] = run;
        }
    }
    __syncthreads();
    for (int i = tid; i < NCH_TOTAL; i += blockDim.x) part[i] = sh[i];
}

__global__ void scan_out_kernel(const int* __restrict__ cntbase, const int* __restrict__ part,
                                int* o0, int* p0, int* o1, int* p1,
                                int* o2, int* p2, int* o3, int* p3) {
    int base, n, ch;
    scan_map(blockIdx.x, base, n, ch);
    int* off; int* pos;
    switch (base) {
        case CNT_T2C: off = o0; pos = p0; break;
        case CNT_C2T: off = o1; pos = p1; break;
        case CNT_C2C: off = o2; pos = p2; break;
        default:      off = o3; pos = p3; break;
    }
    const int tid = threadIdx.x, lane = tid & 31, warp = tid >> 5;
    int i = ch * 1024 + tid;
    int v = (i < n) ? cntbase[base + i] : 0;
    int incl = warp_iscan(v, lane);
    __shared__ int wpart[32];
    if (lane == 31) wpart[warp] = incl;
    __syncthreads();
    if (warp == 0) {
        int wv = wpart[lane];
        int ws = warp_iscan(wv, lane);
        wpart[lane] = ws - wv;
    }
    __syncthreads();
    int excl = part[blockIdx.x] + wpart[warp] + incl - v;
    if (i < n) { off[i] = excl; pos[i] = excl; }
}

__global__ void build4_kernel(const int* __restrict__ s0, const int* __restrict__ d0, int* p0, int* e0,
                              const int* __restrict__ s1, const int* __restrict__ d1, int* p1, int* e1,
                              const int* __restrict__ s2, const int* __restrict__ d2, int* p2, int* e2,
                              const int* __restrict__ s3, const int* __restrict__ d3, int* p3, int* e3,
                              int E0, int E1, int E2, int E3) {
    int i = blockIdx.x * blockDim.x + threadIdx.x;
    if (i < E0) { int sl = atomicAdd(&p0[d0[i]], 1); e0[sl] = s0[i]; return; }
    i -= E0;
    if (i < E1) { int sl = atomicAdd(&p1[d1[i]], 1); e1[sl] = s1[i]; return; }
    i -= E1;
    if (i < E2) { int sl = atomicAdd(&p2[d2[i]], 1); e2[sl] = s2[i]; return; }
    i -= E2;
    if (i < E3) { int sl = atomicAdd(&p3[d3[i]], 1); e3[sl] = s3[i]; }
}

// ---------------- fp16 GEMM core (KC=64, 2-stage cp.async) -------------------
#define AT_BYTES 18432
#define STG_BYTES 36864
#define GEMM_SMEM 73728

struct GemmCore {
    wmma::fragment<wmma::accumulator, 16, 16, 16, float> acc[2][4];
};

__device__ __forceinline__ void gemm_mainloop(
    const __half* __restrict__ A, const __half* __restrict__ W,
    char* smem, uint32_t sb, int bm, int M, int t, int wm, int wn,
    GemmCore& g) {
    #pragma unroll
    for (int i = 0; i < 2; i++)
        #pragma unroll
        for (int j = 0; j < 4; j++) wmma::fill_fragment(g.acc[i][j], 0.0f);

    auto prefetch = [&](int stage, int kb) {
        uint32_t baseA = sb + stage * STG_BYTES;
        uint32_t baseB = baseA + AT_BYTES;
        #pragma unroll
        for (int i = 0; i < 4; i++) {
            int idx = t + i * 256;
            int row = idx >> 3, seg = idx & 7;
            int grow = bm * 128 + row;
            if (grow > M - 1) grow = M - 1;
            CP_ASYNC16(baseA + (uint32_t)(row * 72 + seg * 8) * 2,
                       A + (size_t)grow * DIM + kb * 64 + seg * 8);
            CP_ASYNC16(baseB + (uint32_t)(row * 72 + seg * 8) * 2,
                       W + (size_t)row * DIM + kb * 64 + seg * 8);
        }
        CP_COMMIT();
    };

    prefetch(0, 0);

    for (int kb = 0; kb < 4; kb++) {
        const int s = kb & 1;
        if (kb < 3) { prefetch(s ^ 1, kb + 1); CP_WAIT1(); }
        else        { CP_WAIT0(); }
        __syncthreads();

        __half (*As)[72] = (__half(*)[72])(smem + s * STG_BYTES);
        __half (*Bs)[72] = (__half(*)[72])(smem + s * STG_BYTES + AT_BYTES);

        #pragma unroll
        for (int kk = 0; kk < 4; kk++) {
            wmma::fragment<wmma::matrix_a, 16, 16, 16, __half, wmma::row_major> a[2];
            wmma::fragment<wmma::matrix_b, 16, 16, 16, __half, wmma::col_major> b[4];
            #pragma unroll
            for (int i = 0; i < 2; i++)
                wmma::load_matrix_sync(a[i], &As[wm * 32 + i * 16][kk * 16], 72);
            #pragma unroll
            for (int j = 0; j < 4; j++)
                wmma::load_matrix_sync(b[j], &Bs[wn * 64 + j * 16][kk * 16], 72);
            #pragma unroll
            for (int i = 0; i < 2; i++)
                #pragma unroll
                for (int j = 0; j < 4; j++)
                    wmma::mma_sync(g.acc[i][j], a[i], b[j], g.acc[i][j]);
        }
        __syncthreads();
    }
}

// dual-weight Wh GEMM: grid (mtiles, 4); single-wave epilogue
__global__ __launch_bounds__(256, 2)
void gemm_dual_kernel(const __half* __restrict__ A,
                      const __half* __restrict__ W0, const __half* __restrict__ W1,
                      const float* __restrict__ bias0, const float* __restrict__ bias1,
                      __half* __restrict__ out0, __half* __restrict__ out1, int M) {
    extern __shared__ __align__(16) char smem[];
    const int bm = blockIdx.x, by = blockIdx.y;
    const int which = by >> 1, bn = by & 1;
    const __half* W = which ? W1 : W0;
    const float* bias = which ? bias1 : bias0;
    __half* out = which ? out1 : out0;

    const int t = threadIdx.x;
    const int wid = t >> 5;
    const int wm = wid >> 1, wn = wid & 1;
    const uint32_t sb = smem_u32(smem);

    GemmCore g;
    gemm_mainloop(A, W + (size_t)bn * 128 * DIM, smem, sb, bm, M, t, wm, wn, g);

    float (*Cs)[132] = (float(*)[132])smem;       // 128x132 f32 = 67584 B
    #pragma unroll
    for (int i = 0; i < 2; i++)
        #pragma unroll
        for (int j = 0; j < 4; j++)
            wmma::store_matrix_sync(&Cs[wm * 32 + i * 16][wn * 64 + j * 16], g.acc[i][j],
                                    132, wmma::mem_row_major);
    __syncthreads();
    #pragma unroll
    for (int i = 0; i < 16; i++) {
        int idx = t + i * 256;            // 4096 float4
        int row = idx >> 5, c4 = idx & 31;
        int grow = bm * 128 + row;
        if (grow >= M) continue;
        int col = bn * 128 + c4 * 4;
        float4 v = *(float4*)&Cs[row][c4 * 4];
        float4 bb = *(const float4*)&bias[col];
        v.x += bb.x; v.y += bb.y; v.z += bb.z; v.w += bb.w;
        v.x = v.x >= 0.f ? v.x : 0.01f * v.x;
        v.y = v.y >= 0.f ? v.y : 0.01f * v.y;
        v.z = v.z >= 0.f ? v.z : 0.01f * v.z;
        v.w = v.w >= 0.f ? v.w : 0.01f * v.w;
        half2 h0 = __floats2half2_rn(v.x, v.y);
        half2 h1 = __floats2half2_rn(v.z, v.w);
        *(uint2*)&out[(size_t)grow * DIM + col] =
            make_uint2(*(uint32_t*)&h0, *(uint32_t*)&h1);
    }
}

// final GEMM: +residual, fp32 out, single-wave epilogue. grid (gAll, 2)
__global__ __launch_bounds__(256, 2)
void gemm_final_kernel(const __half* __restrict__ A, const __half* __restrict__ W,
                       const float* __restrict__ bias,
                       const float* __restrict__ resA, const float* __restrict__ resB,
                       int splitM, float* __restrict__ C, int M) {
    extern __shared__ __align__(16) char smem[];
    const int bm = blockIdx.x, bn = blockIdx.y;
    const int t = threadIdx.x;
    const int wid = t >> 5;
    const int wm = wid >> 1, wn = wid & 1;
    const uint32_t sb = smem_u32(smem);

    GemmCore g;
    gemm_mainloop(A, W + (size_t)bn * 128 * DIM, smem, sb, bm, M, t, wm, wn, g);

    float (*Cs)[132] = (float(*)[132])smem;
    #pragma unroll
    for (int i = 0; i < 2; i++)
        #pragma unroll
        for (int j = 0; j < 4; j++)
            wmma::store_matrix_sync(&Cs[wm * 32 + i * 16][wn * 64 + j * 16], g.acc[i][j],
                                    132, wmma::mem_row_major);
    __syncthreads();
    #pragma unroll
    for (int i = 0; i < 16; i++) {
        int idx = t + i * 256;
        int row = idx >> 5, c4 = idx & 31;
        int grow = bm * 128 + row;
        if (grow >= M) continue;
        int col = bn * 128 + c4 * 4;
        float4 v = *(float4*)&Cs[row][c4 * 4];
        float4 bb = *(const float4*)&bias[col];
        v.x += bb.x; v.y += bb.y; v.z += bb.z; v.w += bb.w;
        v.x = v.x >= 0.f ? v.x : 0.01f * v.x;
        v.y = v.y >= 0.f ? v.y : 0.01f * v.y;
        v.z = v.z >= 0.f ? v.z : 0.01f * v.z;
        v.w = v.w >= 0.f ? v.w : 0.01f * v.w;
        const float* rp = (grow < splitM)
            ? &resA[(size_t)grow * DIM + col]
            : &resB[(size_t)(grow - splitM) * DIM + col];
        float4 f = *(const float4*)rp;
        v.x += f.x; v.y += f.y; v.z += f.z; v.w += f.w;
        *(float4*)&C[(size_t)grow * DIM + col] = v;
    }
}

// ---------------- aggregation (both ntypes, one launch) ----------------------
__global__ void agg_all_kernel(
    const __half* __restrict__ Wh_c2t, const int* __restrict__ off_c2t, const int* __restrict__ e_c2t,
    const __half* __restrict__ Wh_t2t, const int* __restrict__ off_t2t, const int* __restrict__ e_t2t,
    const __half* __restrict__ Wh_t2c, const int* __restrict__ off_t2c, const int* __restrict__ e_t2c,
    const __half* __restrict__ Wh_c2c, const int* __restrict__ off_c2c, const int* __restrict__ e_c2c,
    __half* __restrict__ h) {
    int dg = blockIdx.x * 8 + (threadIdx.x >> 5);
    int c = threadIdx.x & 31;
    if (dg >= NT + NC) return;

    const __half* WhA; const int* offA; const int* eA;
    const __half* WhB; const int* offB; const int* eB;
    int d;
    if (dg < NT) {
        d = dg;
        WhA = Wh_c2t; offA = off_c2t; eA = e_c2t;
        WhB = Wh_t2t; offB = off_t2t; eB = e_t2t;
    } else {
        d = dg - NT;
        WhA = Wh_t2c; offA = off_t2c; eA = e_t2c;
        WhB = Wh_c2c; offB = off_c2c; eB = e_c2c;
    }

    const uint4* A4 = (const uint4*)WhA;
    const uint4* B4 = (const uint4*)WhB;

    float acc[8];
    #pragma unroll
    for (int k = 0; k < 8; k++) acc[k] = 0.f;

    auto addv = [&](uint4 v) {
        half2* hv = (half2*)&v;
        #pragma unroll
        for (int k = 0; k < 4; k++) {
            float2 f = __half22float2(hv[k]);
            acc[2 * k] += f.x; acc[2 * k + 1] += f.y;
        }
    };

    auto run = [&](const uint4* T4, const int* e, int s0, int s1) {
        int j = s0;
        for (; j + 3 < s1; j += 4) {
            int i0 = __ldg(&e[j]),     i1 = __ldg(&e[j + 1]);
            int i2 = __ldg(&e[j + 2]), i3 = __ldg(&e[j + 3]);
            uint4 v0 = __ldg(&T4[(size_t)i0 * 32 + c]);
            uint4 v1 = __ldg(&T4[(size_t)i1 * 32 + c]);
            uint4 v2 = __ldg(&T4[(size_t)i2 * 32 + c]);
            uint4 v3 = __ldg(&T4[(size_t)i3 * 32 + c]);
            addv(v0); addv(v1); addv(v2); addv(v3);
        }
        for (; j < s1; j++) addv(__ldg(&T4[(size_t)__ldg(&e[j]) * 32 + c]));
    };

    int s0 = offA[d], s1 = offA[d + 1];
    run(A4, eA, s0, s1);
    float invA = 0.5f / (float)max(s1 - s0, 1);
    float r[8];
    #pragma unroll
    for (int k = 0; k < 8; k++) { r[k] = acc[k] * invA; acc[k] = 0.f; }

    s0 = offB[d]; s1 = offB[d + 1];
    run(B4, eB, s0, s1);
    float invB = 0.5f / (float)max(s1 - s0, 1);
    #pragma unroll
    for (int k = 0; k < 8; k++) r[k] += acc[k] * invB;

    uint4 o;
    half2 p0 = __floats2half2_rn(r[0], r[1]);
    half2 p1 = __floats2half2_rn(r[2], r[3]);
    half2 p2 = __floats2half2_rn(r[4], r[5]);
    half2 p3 = __floats2half2_rn(r[6], r[7]);
    o.x = *(uint32_t*)&p0; o.y = *(uint32_t*)&p1;
    o.z = *(uint32_t*)&p2; o.w = *(uint32_t*)&p3;
    ((uint4*)h)[(size_t)dg * 32 + c] = o;
}

// ---------------- launch -----------------------------------------------------
extern "C" void kernel_launch(void* const* d_in, const int* in_sizes, int n_in,
                              void* d_out, int out_size) {
    const float* feat_table = (const float*)d_in[0];
    const float* feat_col   = (const float*)d_in[1];
    const float* W_t2c = (const float*)d_in[2];  const float* b_t2c = (const float*)d_in[3];
    const float* W_c2t = (const float*)d_in[4];  const float* b_c2t = (const float*)d_in[5];
    const float* W_c2c = (const float*)d_in[6];  const float* b_c2c = (const float*)d_in[7];
    const float* W_t2t = (const float*)d_in[8];  const float* b_t2t = (const float*)d_in[9];
    const float* W_h   = (const float*)d_in[10]; const float* b_h   = (const float*)d_in[11];
    const int* src_t2c = (const int*)d_in[12]; const int* dst_t2c = (const int*)d_in[13];
    const int* src_c2t = (const int*)d_in[14]; const int* dst_c2t = (const int*)d_in[15];
    const int* src_c2c = (const int*)d_in[16]; const int* dst_c2c = (const int*)d_in[17];
    const int* src_t2t = (const int*)d_in[18]; const int* dst_t2t = (const int*)d_in[19];
    float* out = (float*)d_out;

    __half *feat16, *W16, *Wh_t2c, *Wh_c2t, *Wh_c2c, *Wh_t2t, *h16;
    int *cnt, *part;
    int *off_t2c, *pos_t2c, *e_t2c;
    int *off_c2t, *pos_c2t, *e_c2t;
    int *off_c2c, *pos_c2c, *e_c2c;
    int *off_t2t, *pos_t2t, *e_t2t;
    cudaGetSymbolAddress((void**)&feat16, g_feat16);
    cudaGetSymbolAddress((void**)&W16, g_W16);
    cudaGetSymbolAddress((void**)&Wh_t2c, g_Wh_t2c);
    cudaGetSymbolAddress((void**)&Wh_c2t, g_Wh_c2t);
    cudaGetSymbolAddress((void**)&Wh_c2c, g_Wh_c2c);
    cudaGetSymbolAddress((void**)&Wh_t2t, g_Wh_t2t);
    cudaGetSymbolAddress((void**)&h16, g_h16);
    cudaGetSymbolAddress((void**)&cnt, g_cnt);
    cudaGetSymbolAddress((void**)&part, g_part);
    cudaGetSymbolAddress((void**)&off_t2c, g_off_t2c); cudaGetSymbolAddress((void**)&pos_t2c, g_pos_t2c);
    cudaGetSymbolAddress((void**)&e_t2c, g_e_t2c);
    cudaGetSymbolAddress((void**)&off_c2t, g_off_c2t); cudaGetSymbolAddress((void**)&pos_c2t, g_pos_c2t);
    cudaGetSymbolAddress((void**)&e_c2t, g_e_c2t);
    cudaGetSymbolAddress((void**)&off_c2c, g_off_c2c); cudaGetSymbolAddress((void**)&pos_c2c, g_pos_c2c);
    cudaGetSymbolAddress((void**)&e_c2c, g_e_c2c);
    cudaGetSymbolAddress((void**)&off_t2t, g_off_t2t); cudaGetSymbolAddress((void**)&pos_t2t, g_pos_t2t);
    cudaGetSymbolAddress((void**)&e_t2t, g_e_t2t);

    cudaFuncSetAttribute(gemm_dual_kernel,  cudaFuncAttributeMaxDynamicSharedMemorySize, GEMM_SMEM);
    cudaFuncSetAttribute(gemm_final_kernel, cudaFuncAttributeMaxDynamicSharedMemorySize, GEMM_SMEM);

    const int Et2c = in_sizes[12], Ec2t = in_sizes[14], Ec2c = in_sizes[16], Et2t = in_sizes[18];
    const int Eall = Et2c + Ec2t + Ec2c + Et2t;

    cvt_feat_kernel<<<((NT + NC) * DIM / 4 + 255) / 256, 256>>>(feat_table, feat_col, feat16);
    cvt_w_kernel<<<(5 * 16384 + 255) / 256, 256>>>(W_t2c, W_c2t, W_c2c, W_t2t, W_h, W16);

    cudaMemsetAsync(cnt, 0, CNT_TOTAL * sizeof(int), 0);
    hist4_kernel<<<(Eall + 255) / 256, 256>>>(dst_t2c, dst_c2t, dst_c2c, dst_t2t,
                                              cnt, Et2c, Ec2t, Ec2c, Et2t);

    scan_part_kernel<<<NCH_TOTAL, 1024>>>(cnt, part);
    scan_mid_kernel<<<1, 256>>>(part, off_t2c, off_c2t, off_c2c, off_t2t);
    scan_out_kernel<<<NCH_TOTAL, 1024>>>(cnt, part,
                                         off_t2c, pos_t2c, off_c2t, pos_c2t,
                                         off_c2c, pos_c2c, off_t2t, pos_t2t);

    build4_kernel<<<(Eall + 255) / 256, 256>>>(
        src_t2c, dst_t2c, pos_t2c, e_t2c,
        src_c2t, dst_c2t, pos_c2t, e_c2t,
        src_c2c, dst_c2c, pos_c2c, e_c2c,
        src_t2t, dst_t2t, pos_t2t, e_t2t,
        Et2c, Ec2t, Ec2c, Et2t);

    const __half* featT16 = feat16;
    const __half* featC16 = feat16 + (size_t)NT * DIM;
    const int gT = (NT + 127) / 128, gC = (NC + 127) / 128, gAll = (NT + NC + 127) / 128;

    gemm_dual_kernel<<<dim3(gT, 4), 256, GEMM_SMEM>>>(
        featT16, W16 + 0 * DIM * DIM, W16 + 3 * DIM * DIM, b_t2c, b_t2t,
        Wh_t2c, Wh_t2t, NT);
    gemm_dual_kernel<<<dim3(gC, 4), 256, GEMM_SMEM>>>(
        featC16, W16 + 1 * DIM * DIM, W16 + 2 * DIM * DIM, b_c2t, b_c2c,
        Wh_c2t, Wh_c2c, NC);

    agg_all_kernel<<<(NT + NC + 7) / 8, 256>>>(
        Wh_c2t, off_c2t, e_c2t, Wh_t2t, off_t2t, e_t2t,
        Wh_t2c, off_t2c, e_t2c, Wh_c2c, off_c2c, e_c2c, h16);

    gemm_final_kernel<<<dim3(gAll, 2), 256, GEMM_SMEM>>>(
        h16, W16 + 4 * DIM * DIM, b_h, feat_table, feat_col, NT, out, NT + NC);
}

// round 11
// speedup vs baseline: 1.0093x; 1.0093x over previous
#include <cuda_runtime.h>
#include <cuda_fp16.h>
#include <mma.h>
#include <cstdint>

using namespace nvcuda;

#define NT 20000
#define NC 80000
#define DIM 256
#define E_T2C 320000
#define E_C2T 320000
#define E_C2C 640000
#define E_T2T 160000

// ---------------- scratch (device globals; no allocations allowed) ----------
__device__ __half g_feat16[(size_t)(NT + NC) * DIM];       // [table | column]
__device__ __half g_W16[5 * DIM * DIM];                    // t2c,c2t,c2c,t2t,h
__device__ __half g_Wh_t2c[(size_t)NT * DIM];
__device__ __half g_Wh_c2t[(size_t)NC * DIM];
__device__ __half g_Wh_c2c[(size_t)NC * DIM];
__device__ __half g_Wh_t2t[(size_t)NT * DIM];
__device__ __half g_h16[(size_t)(NT + NC) * DIM];

#define CNT_T2C 0
#define CNT_C2T NC
#define CNT_C2C (NC + NT)
#define CNT_T2T (NC + NT + NC)
#define CNT_TOTAL (2 * NC + 2 * NT)
__device__ int g_cnt[CNT_TOTAL];
__device__ int g_off_t2c[NC + 1]; __device__ int g_pos_t2c[NC]; __device__ int g_e_t2c[E_T2C];
__device__ int g_off_c2t[NT + 1]; __device__ int g_pos_c2t[NT]; __device__ int g_e_c2t[E_C2T];
__device__ int g_off_c2c[NC + 1]; __device__ int g_pos_c2c[NC]; __device__ int g_e_c2c[E_C2C];
__device__ int g_off_t2t[NT + 1]; __device__ int g_pos_t2t[NT]; __device__ int g_e_t2t[E_T2T];

// scan partials: chunks per etype: NC->79, NT->20, NC->79, NT->20
#define NCH0 79
#define NCH1 20
#define NCH2 79
#define NCH3 20
#define NCH_TOTAL (NCH0 + NCH1 + NCH2 + NCH3)   // 198
__device__ int g_part[NCH_TOTAL];

// ---------------- helpers ----------------------------------------------------
__device__ __forceinline__ uint32_t smem_u32(const void* p) {
    uint32_t a;
    asm("{ .reg .u64 t; cvta.to.shared.u64 t, %1; cvt.u32.u64 %0, t; }" : "=r"(a) : "l"(p));
    return a;
}
#define CP_ASYNC16(dst, src) \
    asm volatile("cp.async.cg.shared.global [%0], [%1], 16;" :: "r"(dst), "l"(src))
#define CP_COMMIT() asm volatile("cp.async.commit_group;" ::: "memory")
#define CP_WAIT2() asm volatile("cp.async.wait_group 2;" ::: "memory")

__device__ __forceinline__ int warp_iscan(int v, int lane) {
    #pragma unroll
    for (int ofs = 1; ofs < 32; ofs <<= 1) {
        int t = __shfl_up_sync(0xffffffffu, v, ofs);
        if (lane >= ofs) v += t;
    }
    return v;
}

__device__ __forceinline__ void scan_map(int b, int& base, int& n, int& ch) {
    if (b < NCH0)                      { base = CNT_T2C; n = NC; ch = b; }
    else if (b < NCH0 + NCH1)          { base = CNT_C2T; n = NT; ch = b - NCH0; }
    else if (b < NCH0 + NCH1 + NCH2)   { base = CNT_C2C; n = NC; ch = b - NCH0 - NCH1; }
    else                               { base = CNT_T2T; n = NT; ch = b - NCH0 - NCH1 - NCH2; }
}

// ---------------- conversion kernels -----------------------------------------
__global__ void cvt_feat_kernel(const float* __restrict__ ft, const float* __restrict__ fc,
                                __half* __restrict__ dst) {
    int i = blockIdx.x * blockDim.x + threadIdx.x;
    const int n4T = NT * DIM / 4;
    const int n4 = (NT + NC) * DIM / 4;
    if (i >= n4) return;
    float4 v = (i < n4T) ? ((const float4*)ft)[i] : ((const float4*)fc)[i - n4T];
    half2* d2 = (half2*)dst;
    d2[2 * i]     = __floats2half2_rn(v.x, v.y);
    d2[2 * i + 1] = __floats2half2_rn(v.z, v.w);
}

__global__ void cvt_w_kernel(const float* __restrict__ w0, const float* __restrict__ w1,
                             const float* __restrict__ w2, const float* __restrict__ w3,
                             const float* __restrict__ w4, __half* __restrict__ dst) {
    int i = blockIdx.x * blockDim.x + threadIdx.x;
    if (i >= 5 * 16384) return;
    const float* srcs[5] = {w0, w1, w2, w3, w4};
    const float* s = srcs[i >> 14];
    int j = i & 16383;
    float4 v = ((const float4*)s)[j];
    half2* d2 = (half2*)dst;
    d2[2 * i]     = __floats2half2_rn(v.x, v.y);
    d2[2 * i + 1] = __floats2half2_rn(v.z, v.w);
}

// ---------------- graph preprocessing ----------------------------------------
__global__ void hist4_kernel(const int* __restrict__ d0, const int* __restrict__ d1,
                             const int* __restrict__ d2, const int* __restrict__ d3,
                             int* __restrict__ cnt,
                             int E0, int E1, int E2, int E3) {
    int i = blockIdx.x * blockDim.x + threadIdx.x;
    if (i < E0) { atomicAdd(&cnt[CNT_T2C + d0[i]], 1); return; }
    i -= E0;
    if (i < E1) { atomicAdd(&cnt[CNT_C2T + d1[i]], 1); return; }
    i -= E1;
    if (i < E2) { atomicAdd(&cnt[CNT_C2C + d2[i]], 1); return; }
    i -= E2;
    if (i < E3) { atomicAdd(&cnt[CNT_T2T + d3[i]], 1); }
}

__global__ void scan_part_kernel(const int* __restrict__ cntbase, int* __restrict__ part) {
    int base, n, ch;
    scan_map(blockIdx.x, base, n, ch);
    const int tid = threadIdx.x, lane = tid & 31, warp = tid >> 5;
    int i = ch * 1024 + tid;
    int v = (i < n) ? cntbase[base + i] : 0;
    #pragma unroll
    for (int ofs = 16; ofs > 0; ofs >>= 1) v += __shfl_down_sync(0xffffffffu, v, ofs);
    __shared__ int ws[32];
    if (lane == 0) ws[warp] = v;
    __syncthreads();
    if (warp == 0) {
        int s = ws[lane];
        #pragma unroll
        for (int ofs = 16; ofs > 0; ofs >>= 1) s += __shfl_down_sync(0xffffffffu, s, ofs);
        if (lane == 0) part[blockIdx.x] = s;
    }
}

__global__ void scan_mid_kernel(int* __restrict__ part,
                                int* o0, int* o1, int* o2, int* o3) {
    __shared__ int sh[NCH_TOTAL];
    const int tid = threadIdx.x;
    for (int i = tid; i < NCH_TOTAL; i += blockDim.x) sh[i] = part[i];
    __syncthreads();
    if (tid == 0) {
        const int bnd[5] = {0, NCH0, NCH0 + NCH1, NCH0 + NCH1 + NCH2, NCH_TOTAL};
        int* offs[4] = {o0, o1, o2, o3};
        const int nlist[4] = {NC, NT, NC, NT};
        for (int e = 0; e < 4; e++) {
            int run = 0;
            for (int b = bnd[e]; b < bnd[e + 1]; b++) { int v = sh[b]; sh[b] = run; run += v; }
            offs[e][nlist[e]] = run;
        }
    }
    __syncthreads();
    for (int i = tid; i < NCH_TOTAL; i += blockDim.x) part[i] = sh[i];
}

__global__ void scan_out_kernel(const int* __restrict__ cntbase, const int* __restrict__ part,
                                int* o0, int* p0, int* o1, int* p1,
                                int* o2, int* p2, int* o3, int* p3) {
    int base, n, ch;
    scan_map(blockIdx.x, base, n, ch);
    int* off; int* pos;
    switch (base) {
        case CNT_T2C: off = o0; pos = p0; break;
        case CNT_C2T: off = o1; pos = p1; break;
        case CNT_C2C: off = o2; pos = p2; break;
        default:      off = o3; pos = p3; break;
    }
    const int tid = threadIdx.x, lane = tid & 31, warp = tid >> 5;
    int i = ch * 1024 + tid;
    int v = (i < n) ? cntbase[base + i] : 0;
    int incl = warp_iscan(v, lane);
    __shared__ int wpart[32];
    if (lane == 31) wpart[warp] = incl;
    __syncthreads();
    if (warp == 0) {
        int wv = wpart[lane];
        int ws = warp_iscan(wv, lane);
        wpart[lane] = ws - wv;
    }
    __syncthreads();
    int excl = part[blockIdx.x] + wpart[warp] + incl - v;
    if (i < n) { off[i] = excl; pos[i] = excl; }
}

__global__ void build4_kernel(const int* __restrict__ s0, const int* __restrict__ d0, int* p0, int* e0,
                              const int* __restrict__ s1, const int* __restrict__ d1, int* p1, int* e1,
                              const int* __restrict__ s2, const int* __restrict__ d2, int* p2, int* e2,
                              const int* __restrict__ s3, const int* __restrict__ d3, int* p3, int* e3,
                              int E0, int E1, int E2, int E3) {
    int i = blockIdx.x * blockDim.x + threadIdx.x;
    if (i < E0) { int sl = atomicAdd(&p0[d0[i]], 1); e0[sl] = s0[i]; return; }
    i -= E0;
    if (i < E1) { int sl = atomicAdd(&p1[d1[i]], 1); e1[sl] = s1[i]; return; }
    i -= E1;
    if (i < E2) { int sl = atomicAdd(&p2[d2[i]], 1); e2[sl] = s2[i]; return; }
    i -= E2;
    if (i < E3) { int sl = atomicAdd(&p3[d3[i]], 1); e3[sl] = s3[i]; }
}

// ---------------- fp16 GEMM core (KC=32, 4-stage cp.async) -------------------
// Tile 128x128, 256 thr, warp tile 32x64. K = 256 in 8 chunks of 32 halfs.
// stage: A[128][40]h (10240B) + B[128][40]h = 20480B; x4 = 81920B dyn smem.
#define AT_BYTES 10240
#define STG_BYTES 20480
#define GEMM_SMEM 81920

struct GemmCore {
    wmma::fragment<wmma::accumulator, 16, 16, 16, float> acc[2][4];
};

__device__ __forceinline__ void gemm_mainloop(
    const __half* __restrict__ A, const __half* __restrict__ W,
    char* smem, uint32_t sb, int bm, int M, int t, int wm, int wn,
    GemmCore& g) {
    #pragma unroll
    for (int i = 0; i < 2; i++)
        #pragma unroll
        for (int j = 0; j < 4; j++) wmma::fill_fragment(g.acc[i][j], 0.0f);

    // per chunk: A,B each 128 rows x 32 halfs = 512 x 16B; 2/thread each
    auto prefetch = [&](int stage, int kb) {
        uint32_t baseA = sb + stage * STG_BYTES;
        uint32_t baseB = baseA + AT_BYTES;
        #pragma unroll
        for (int i = 0; i < 2; i++) {
            int idx = t + i * 256;
            int row = idx >> 2, seg = idx & 3;
            int grow = bm * 128 + row;
            if (grow > M - 1) grow = M - 1;
            CP_ASYNC16(baseA + (uint32_t)(row * 40 + seg * 8) * 2,
                       A + (size_t)grow * DIM + kb * 32 + seg * 8);
            CP_ASYNC16(baseB + (uint32_t)(row * 40 + seg * 8) * 2,
                       W + (size_t)row * DIM + kb * 32 + seg * 8);
        }
        CP_COMMIT();
    };

    prefetch(0, 0);
    prefetch(1, 1);
    prefetch(2, 2);

    for (int kb = 0; kb < 8; kb++) {
        CP_WAIT2();                 // group kb complete (cadence kept via empty commits)
        __syncthreads();            // all warps done reading stage (kb-1)&3

        if (kb < 5) prefetch((kb + 3) & 3, kb + 3);
        else        CP_COMMIT();    // empty group keeps wait_group accounting exact

        const int s = kb & 3;
        __half (*As)[40] = (__half(*)[40])(smem + s * STG_BYTES);
        __half (*Bs)[40] = (__half(*)[40])(smem + s * STG_BYTES + AT_BYTES);

        #pragma unroll
        for (int kk = 0; kk < 2; kk++) {
            wmma::fragment<wmma::matrix_a, 16, 16, 16, __half, wmma::row_major> a[2];
            wmma::fragment<wmma::matrix_b, 16, 16, 16, __half, wmma::col_major> b[4];
            #pragma unroll
            for (int i = 0; i < 2; i++)
                wmma::load_matrix_sync(a[i], &As[wm * 32 + i * 16][kk * 16], 40);
            #pragma unroll
            for (int j = 0; j < 4; j++)
                wmma::load_matrix_sync(b[j], &Bs[wn * 64 + j * 16][kk * 16], 40);
            #pragma unroll
            for (int i = 0; i < 2; i++)
                #pragma unroll
                for (int j = 0; j < 4; j++)
                    wmma::mma_sync(g.acc[i][j], a[i], b[j], g.acc[i][j]);
        }
    }
    __syncthreads();                // protect smem reuse by epilogue
}

// dual-weight Wh GEMM: grid (mtiles, 4); y>>1 selects weight/out, y&1 = col half
__global__ __launch_bounds__(256, 2)
void gemm_dual_kernel(const __half* __restrict__ A,
                      const __half* __restrict__ W0, const __half* __restrict__ W1,
                      const float* __restrict__ bias0, const float* __restrict__ bias1,
                      __half* __restrict__ out0, __half* __restrict__ out1, int M) {
    extern __shared__ __align__(16) char smem[];
    const int bm = blockIdx.x, by = blockIdx.y;
    const int which = by >> 1, bn = by & 1;
    const __half* W = which ? W1 : W0;
    const float* bias = which ? bias1 : bias0;
    __half* out = which ? out1 : out0;

    const int t = threadIdx.x;
    const int wid = t >> 5;
    const int wm = wid >> 1, wn = wid & 1;
    const uint32_t sb = smem_u32(smem);

    GemmCore g;
    gemm_mainloop(A, W + (size_t)bn * 128 * DIM, smem, sb, bm, M, t, wm, wn, g);

    float (*Cs)[32][68] = (float(*)[32][68])smem;   // two warp-waves, 34816 B
    #pragma unroll
    for (int w = 0; w < 2; w++) {
        if ((wid >> 2) == w) {
            int slot = wid & 3;
            #pragma unroll
            for (int i = 0; i < 2; i++)
                #pragma unroll
                for (int j = 0; j < 4; j++)
                    wmma::store_matrix_sync(&Cs[slot][i * 16][j * 16], g.acc[i][j], 68,
                                            wmma::mem_row_major);
        }
        __syncthreads();
        #pragma unroll
        for (int i = 0; i < 8; i++) {
            int idx = t + i * 256;
            int slot = idx >> 9;
            int within = idx & 511;
            int row = within >> 4, c4 = within & 15;
            int grow = bm * 128 + (w * 2 + (slot >> 1)) * 32 + row;
            if (grow >= M) continue;
            int col = bn * 128 + (slot & 1) * 64 + c4 * 4;
            float4 v = *(float4*)&Cs[slot][row][c4 * 4];
            float4 bb = *(const float4*)&bias[col];
            v.x += bb.x; v.y += bb.y; v.z += bb.z; v.w += bb.w;
            v.x = v.x >= 0.f ? v.x : 0.01f * v.x;
            v.y = v.y >= 0.f ? v.y : 0.01f * v.y;
            v.z = v.z >= 0.f ? v.z : 0.01f * v.z;
            v.w = v.w >= 0.f ? v.w : 0.01f * v.w;
            half2 h0 = __floats2half2_rn(v.x, v.y);
            half2 h1 = __floats2half2_rn(v.z, v.w);
            *(uint2*)&out[(size_t)grow * DIM + col] =
                make_uint2(*(uint32_t*)&h0, *(uint32_t*)&h1);
        }
        __syncthreads();
    }
}

// final GEMM: +residual, fp32 out. grid (mtiles, 2)
__global__ __launch_bounds__(256, 2)
void gemm_final_kernel(const __half* __restrict__ A, const __half* __restrict__ W,
                       const float* __restrict__ bias,
                       const float* __restrict__ resA, const float* __restrict__ resB,
                       int splitM, float* __restrict__ C, int M) {
    extern __shared__ __align__(16) char smem[];
    const int bm = blockIdx.x, bn = blockIdx.y;
    const int t = threadIdx.x;
    const int wid = t >> 5;
    const int wm = wid >> 1, wn = wid & 1;
    const uint32_t sb = smem_u32(smem);

    GemmCore g;
    gemm_mainloop(A, W + (size_t)bn * 128 * DIM, smem, sb, bm, M, t, wm, wn, g);

    float (*Cs)[32][68] = (float(*)[32][68])smem;
    #pragma unroll
    for (int w = 0; w < 2; w++) {
        if ((wid >> 2) == w) {
            int slot = wid & 3;
            #pragma unroll
            for (int i = 0; i < 2; i++)
                #pragma unroll
                for (int j = 0; j < 4; j++)
                    wmma::store_matrix_sync(&Cs[slot][i * 16][j * 16], g.acc[i][j], 68,
                                            wmma::mem_row_major);
        }
        __syncthreads();
        #pragma unroll
        for (int i = 0; i < 8; i++) {
            int idx = t + i * 256;
            int slot = idx >> 9;
            int within = idx & 511;
            int row = within >> 4, c4 = within & 15;
            int grow = bm * 128 + (w * 2 + (slot >> 1)) * 32 + row;
            if (grow >= M) continue;
            int col = bn * 128 + (slot & 1) * 64 + c4 * 4;
            float4 v = *(float4*)&Cs[slot][row][c4 * 4];
            float4 bb = *(const float4*)&bias[col];
            v.x += bb.x; v.y += bb.y; v.z += bb.z; v.w += bb.w;
            v.x = v.x >= 0.f ? v.x : 0.01f * v.x;
            v.y = v.y >= 0.f ? v.y : 0.01f * v.y;
            v.z = v.z >= 0.f ? v.z : 0.01f * v.z;
            v.w = v.w >= 0.f ? v.w : 0.01f * v.w;
            size_t gi = (size_t)grow * DIM + col;
            const float* rp = (grow < splitM)
                ? &resA[(size_t)grow * DIM + col]
                : &resB[(size_t)(grow - splitM) * DIM + col];
            float4 f = *(const float4*)rp;
            v.x += f.x; v.y += f.y; v.z += f.z; v.w += f.w;
            *(float4*)&C[gi] = v;
        }
        __syncthreads();
    }
}

// ---------------- aggregation (fp16 in/out, fp32 accum, 4x MLP) --------------
__global__ void agg2_kernel(const __half* __restrict__ WhA, const int* __restrict__ offA,
                            const int* __restrict__ eA,
                            const __half* __restrict__ WhB, const int* __restrict__ offB,
                            const int* __restrict__ eB,
                            __half* __restrict__ h, int n) {
    int d = blockIdx.x * 8 + (threadIdx.x >> 5);
    int c = threadIdx.x & 31;
    if (d >= n) return;

    const uint4* A4 = (const uint4*)WhA;
    const uint4* B4 = (const uint4*)WhB;

    float acc[8];
    #pragma unroll
    for (int k = 0; k < 8; k++) acc[k] = 0.f;

    auto addv = [&](uint4 v) {
        half2* hv = (half2*)&v;
        #pragma unroll
        for (int k = 0; k < 4; k++) {
            float2 f = __half22float2(hv[k]);
            acc[2 * k] += f.x; acc[2 * k + 1] += f.y;
        }
    };

    auto run = [&](const uint4* T4, const int* e, int s0, int s1) {
        int j = s0;
        for (; j + 3 < s1; j += 4) {
            int i0 = __ldg(&e[j]),     i1 = __ldg(&e[j + 1]);
            int i2 = __ldg(&e[j + 2]), i3 = __ldg(&e[j + 3]);
            uint4 v0 = __ldg(&T4[(size_t)i0 * 32 + c]);
            uint4 v1 = __ldg(&T4[(size_t)i1 * 32 + c]);
            uint4 v2 = __ldg(&T4[(size_t)i2 * 32 + c]);
            uint4 v3 = __ldg(&T4[(size_t)i3 * 32 + c]);
            addv(v0); addv(v1); addv(v2); addv(v3);
        }
        for (; j < s1; j++) addv(__ldg(&T4[(size_t)__ldg(&e[j]) * 32 + c]));
    };

    int s0 = offA[d], s1 = offA[d + 1];
    run(A4, eA, s0, s1);
    float invA = 0.5f / (float)max(s1 - s0, 1);
    float r[8];
    #pragma unroll
    for (int k = 0; k < 8; k++) { r[k] = acc[k] * invA; acc[k] = 0.f; }

    s0 = offB[d]; s1 = offB[d + 1];
    run(B4, eB, s0, s1);
    float invB = 0.5f / (float)max(s1 - s0, 1);
    #pragma unroll
    for (int k = 0; k < 8; k++) r[k] += acc[k] * invB;

    uint4 o;
    half2 p0 = __floats2half2_rn(r[0], r[1]);
    half2 p1 = __floats2half2_rn(r[2], r[3]);
    half2 p2 = __floats2half2_rn(r[4], r[5]);
    half2 p3 = __floats2half2_rn(r[6], r[7]);
    o.x = *(uint32_t*)&p0; o.y = *(uint32_t*)&p1;
    o.z = *(uint32_t*)&p2; o.w = *(uint32_t*)&p3;
    ((uint4*)h)[(size_t)d * 32 + c] = o;
}

// ---------------- launch -----------------------------------------------------
extern "C" void kernel_launch(void* const* d_in, const int* in_sizes, int n_in,
                              void* d_out, int out_size) {
    const float* feat_table = (const float*)d_in[0];
    const float* feat_col   = (const float*)d_in[1];
    const float* W_t2c = (const float*)d_in[2];  const float* b_t2c = (const float*)d_in[3];
    const float* W_c2t = (const float*)d_in[4];  const float* b_c2t = (const float*)d_in[5];
    const float* W_c2c = (const float*)d_in[6];  const float* b_c2c = (const float*)d_in[7];
    const float* W_t2t = (const float*)d_in[8];  const float* b_t2t = (const float*)d_in[9];
    const float* W_h   = (const float*)d_in[10]; const float* b_h   = (const float*)d_in[11];
    const int* src_t2c = (const int*)d_in[12]; const int* dst_t2c = (const int*)d_in[13];
    const int* src_c2t = (const int*)d_in[14]; const int* dst_c2t = (const int*)d_in[15];
    const int* src_c2c = (const int*)d_in[16]; const int* dst_c2c = (const int*)d_in[17];
    const int* src_t2t = (const int*)d_in[18]; const int* dst_t2t = (const int*)d_in[19];
    float* out = (float*)d_out;

    __half *feat16, *W16, *Wh_t2c, *Wh_c2t, *Wh_c2c, *Wh_t2t, *h16;
    int *cnt, *part;
    int *off_t2c, *pos_t2c, *e_t2c;
    int *off_c2t, *pos_c2t, *e_c2t;
    int *off_c2c, *pos_c2c, *e_c2c;
    int *off_t2t, *pos_t2t, *e_t2t;
    cudaGetSymbolAddress((void**)&feat16, g_feat16);
    cudaGetSymbolAddress((void**)&W16, g_W16);
    cudaGetSymbolAddress((void**)&Wh_t2c, g_Wh_t2c);
    cudaGetSymbolAddress((void**)&Wh_c2t, g_Wh_c2t);
    cudaGetSymbolAddress((void**)&Wh_c2c, g_Wh_c2c);
    cudaGetSymbolAddress((void**)&Wh_t2t, g_Wh_t2t);
    cudaGetSymbolAddress((void**)&h16, g_h16);
    cudaGetSymbolAddress((void**)&cnt, g_cnt);
    cudaGetSymbolAddress((void**)&part, g_part);
    cudaGetSymbolAddress((void**)&off_t2c, g_off_t2c); cudaGetSymbolAddress((void**)&pos_t2c, g_pos_t2c);
    cudaGetSymbolAddress((void**)&e_t2c, g_e_t2c);
    cudaGetSymbolAddress((void**)&off_c2t, g_off_c2t); cudaGetSymbolAddress((void**)&pos_c2t, g_pos_c2t);
    cudaGetSymbolAddress((void**)&e_c2t, g_e_c2t);
    cudaGetSymbolAddress((void**)&off_c2c, g_off_c2c); cudaGetSymbolAddress((void**)&pos_c2c, g_pos_c2c);
    cudaGetSymbolAddress((void**)&e_c2c, g_e_c2c);
    cudaGetSymbolAddress((void**)&off_t2t, g_off_t2t); cudaGetSymbolAddress((void**)&pos_t2t, g_pos_t2t);
    cudaGetSymbolAddress((void**)&e_t2t, g_e_t2t);

    cudaFuncSetAttribute(gemm_dual_kernel,  cudaFuncAttributeMaxDynamicSharedMemorySize, GEMM_SMEM);
    cudaFuncSetAttribute(gemm_final_kernel, cudaFuncAttributeMaxDynamicSharedMemorySize, GEMM_SMEM);

    const int Et2c = in_sizes[12], Ec2t = in_sizes[14], Ec2c = in_sizes[16], Et2t = in_sizes[18];
    const int Eall = Et2c + Ec2t + Ec2c + Et2t;

    cvt_feat_kernel<<<((NT + NC) * DIM / 4 + 255) / 256, 256>>>(feat_table, feat_col, feat16);
    cvt_w_kernel<<<(5 * 16384 + 255) / 256, 256>>>(W_t2c, W_c2t, W_c2c, W_t2t, W_h, W16);

    cudaMemsetAsync(cnt, 0, CNT_TOTAL * sizeof(int), 0);
    hist4_kernel<<<(Eall + 255) / 256, 256>>>(dst_t2c, dst_c2t, dst_c2c, dst_t2t,
                                              cnt, Et2c, Ec2t, Ec2c, Et2t);

    scan_part_kernel<<<NCH_TOTAL, 1024>>>(cnt, part);
    scan_mid_kernel<<<1, 256>>>(part, off_t2c, off_c2t, off_c2c, off_t2t);
    scan_out_kernel<<<NCH_TOTAL, 1024>>>(cnt, part,
                                         off_t2c, pos_t2c, off_c2t, pos_c2t,
                                         off_c2c, pos_c2c, off_t2t, pos_t2t);

    build4_kernel<<<(Eall + 255) / 256, 256>>>(
        src_t2c, dst_t2c, pos_t2c, e_t2c,
        src_c2t, dst_c2t, pos_c2t, e_c2t,
        src_c2c, dst_c2c, pos_c2c, e_c2c,
        src_t2t, dst_t2t, pos_t2t, e_t2t,
        Et2c, Ec2t, Ec2c, Et2t);

    const __half* featT16 = feat16;
    const __half* featC16 = feat16 + (size_t)NT * DIM;
    const int gT = (NT + 127) / 128, gC = (NC + 127) / 128, gAll = (NT + NC + 127) / 128;

    gemm_dual_kernel<<<dim3(gT, 4), 256, GEMM_SMEM>>>(
        featT16, W16 + 0 * DIM * DIM, W16 + 3 * DIM * DIM, b_t2c, b_t2t,
        Wh_t2c, Wh_t2t, NT);
    gemm_dual_kernel<<<dim3(gC, 4), 256, GEMM_SMEM>>>(
        featC16, W16 + 1 * DIM * DIM, W16 + 2 * DIM * DIM, b_c2t, b_c2c,
        Wh_c2t, Wh_c2c, NC);

    agg2_kernel<<<(NT + 7) / 8, 256>>>(Wh_c2t, off_c2t, e_c2t, Wh_t2t, off_t2t, e_t2t, h16, NT);
    agg2_kernel<<<(NC + 7) / 8, 256>>>(Wh_t2c, off_t2c, e_t2c, Wh_c2c, off_c2c, e_c2c,
                                       h16 + (size_t)NT * DIM, NC);

    gemm_final_kernel<<<dim3(gAll, 2), 256, GEMM_SMEM>>>(
        h16, W16 + 4 * DIM * DIM, b_h, feat_table, feat_col, NT, out, NT + NC);
}